// round 10
// baseline (speedup 1.0000x reference)
#include <cuda_runtime.h>
#include <cstdint>

#define A_TOT 68
#define TROWS 32                 // rows per warp-tile
#define TPB   64                 // 2 independent warps per block
#define F4PW  (TROWS * 17)       // 544 float4 per warp-tile stage (8704 B)
#define MAXW  2048
#define L2E   1.4426950408889634f
#define LN2   0.6931471805599453f

__device__ float g_partials[MAXW];
__device__ unsigned int g_count = 0;

__constant__ unsigned char c_seg_of[A_TOT] = {
    0,0,0, 1,1,1, 2,2,2,2,
    3,3,3,3,3,3,3,3,3,3,3,3,3,3,3,3,3,3,3,3,3,3,3,3,3,
    4,4,4,4,4,4,4,4,4,4,4,4,4,4,4,4,4,4,4,4,4,4,4,4,4,
    5,5,5,5,5,5,5,5
};
__constant__ int c_seg_beg[6] = {0, 3, 6, 10, 35, 60};
__constant__ int c_seg_end[6] = {3, 6, 10, 35, 60, 68};

// ---------------------------------------------------------------------------
__device__ __forceinline__ void cp16(void* sdst, const void* gsrc) {
    uint32_t s = (uint32_t)__cvta_generic_to_shared(sdst);
    asm volatile("cp.async.cg.shared.global [%0], [%1], 16;\n" :: "r"(s), "l"(gsrc));
}
__device__ __forceinline__ void cp_commit() { asm volatile("cp.async.commit_group;\n"); }
__device__ __forceinline__ void cp_wait1()  { asm volatile("cp.async.wait_group 1;\n"); }

__device__ __forceinline__ float ex2a(float x) {
    float r; asm("ex2.approx.f32 %0,%1;" : "=f"(r) : "f"(x)); return r;
}
__device__ __forceinline__ float lg2a(float x) {
    float r; asm("lg2.approx.f32 %0,%1;" : "=f"(r) : "f"(x)); return r;
}
__device__ __forceinline__ float rcpa(float x) {
    float r; asm("rcp.approx.f32 %0,%1;" : "=f"(r) : "f"(x)); return r;
}

// Per-element (log2 space; nxl = -x*log2e precomputed):
//   u = z*L2E; e = 2^u; S += e; V += e*(u+nxl)
// Segment loss (log2 units) = inv_n*(V/S - lg2 S); * ln2 once per thread.
__device__ __forceinline__ void stepe(float& S, float& V, float z, float nxl) {
    float u = z * L2E;
    float e = ex2a(u);
    S += e;
    V = fmaf(e, u + nxl, V);
}
__device__ __forceinline__ float fin(float S, float V, float inv_n) {
    return inv_n * fmaf(V, rcpa(S), -lg2a(S));
}

// ---------------------------------------------------------------------------
// Warp-autonomous kernel: each warp streams its own 32-row tiles through a
// private 2-stage cp.async double buffer. NO block barriers in the main loop.
// One lane = one full row. Last finishing warp does the deterministic final
// reduction over all per-warp partials.
// ---------------------------------------------------------------------------
__global__ void __launch_bounds__(TPB, 6)
fused_kernel(const float* __restrict__ cur,
             const float* __restrict__ prev,
             float* __restrict__ out,
             int W, int nwarps, float inv_W) {
    __shared__ float4 buf[2][2][F4PW];   // [warp][stage][...]  34816 B
    __shared__ float4 sx4[2][17];        // per-warp nxl table (68 floats)
    __shared__ float  sm6[2][6], sls6[2][6];

    const int t    = threadIdx.x;
    const int wid  = t >> 5;
    const int lane = t & 31;
    const int gw   = blockIdx.x * 2 + wid;        // global warp id
    const int ntiles = (W + TROWS - 1) / TROWS;
    const int step   = nwarps;

    float4* b0 = buf[wid][0];
    float4* b1 = buf[wid][1];

    // ---- initial prefetches: tiles gw and gw+step ----
    {
        const int tl = gw;
        if (tl < ntiles) {
            const float4* g = (const float4*)prev + (size_t)tl * F4PW + lane;
            const int rows = min(TROWS, W - tl * TROWS);
            if (rows == TROWS) {
#pragma unroll
                for (int k = 0; k < 17; k++) cp16(&b0[lane + 32 * k], g + 32 * k);
            } else {
                const int n4 = rows * 17;
#pragma unroll
                for (int k = 0; k < 17; k++)
                    if (lane + 32 * k < n4)  cp16(&b0[lane + 32 * k], g + 32 * k);
            }
        }
        cp_commit();
        const int tn = gw + step;
        if (tn < ntiles) {
            const float4* g = (const float4*)prev + (size_t)tn * F4PW + lane;
            const int rows = min(TROWS, W - tn * TROWS);
            if (rows == TROWS) {
#pragma unroll
                for (int k = 0; k < 17; k++) cp16(&b1[lane + 32 * k], g + 32 * k);
            } else {
                const int n4 = rows * 17;
#pragma unroll
                for (int k = 0; k < 17; k++)
                    if (lane + 32 * k < n4)  cp16(&b1[lane + 32 * k], g + 32 * k);
            }
        }
        cp_commit();
    }

    // ---- per-warp x table: nxl = -(log2-space log_softmax(cur)) ------------
    float* sx = (float*)sx4[wid];
    for (int i = lane; i < A_TOT; i += 32) sx[i] = cur[i] * L2E;
    __syncwarp();
    if (lane < 6) {
        int b = c_seg_beg[lane], e = c_seg_end[lane];
        float m = -1e30f;
        for (int i = b; i < e; i++) m = fmaxf(m, sx[i]);
        float sum = 0.f;
        for (int i = b; i < e; i++) sum += ex2a(sx[i] - m);
        sm6[wid][lane]  = m;
        sls6[wid][lane] = lg2a(sum);
    }
    __syncwarp();
    for (int i = lane; i < A_TOT; i += 32) {
        int sg = c_seg_of[i];
        sx[i] = -(sx[i] - sm6[wid][sg] - sls6[wid][sg]);
    }
    __syncwarp();

    // ---- warp-private pipelined loop (no block barriers) ----
    float acc = 0.f;                     // log2 units
    int stage = 0;
    const float4* sp = sx4[wid];
    for (int tile = gw; tile < ntiles; tile += step) {
        cp_wait1();                      // this tile's group complete
        __syncwarp();                    // cross-lane smem visibility

        const int rows_here = min(TROWS, W - tile * TROWS);
        float4* bs = (stage == 0) ? b0 : b1;
        if (lane < rows_here) {
            const float4* rp = &bs[lane * 17];   // conflict-free LDS.128
            float S0=0,V0=0, S1=0,V1=0, S2=0,V2=0, S3=0,V3=0, S4=0,V4=0, S5=0,V5=0;
            float4 z, q;
            z = rp[0]; q = sp[0];
            stepe(S0,V0,z.x,q.x); stepe(S0,V0,z.y,q.y);
            stepe(S0,V0,z.z,q.z); stepe(S1,V1,z.w,q.w);
            z = rp[1]; q = sp[1];
            stepe(S1,V1,z.x,q.x); stepe(S1,V1,z.y,q.y);
            stepe(S2,V2,z.z,q.z); stepe(S2,V2,z.w,q.w);
            z = rp[2]; q = sp[2];
            stepe(S2,V2,z.x,q.x); stepe(S2,V2,z.y,q.y);
            stepe(S3,V3,z.z,q.z); stepe(S3,V3,z.w,q.w);
#pragma unroll
            for (int j = 3; j < 8; j++) {            // elems 12..31
                z = rp[j]; q = sp[j];
                stepe(S3,V3,z.x,q.x); stepe(S3,V3,z.y,q.y);
                stepe(S3,V3,z.z,q.z); stepe(S3,V3,z.w,q.w);
            }
            z = rp[8]; q = sp[8];
            stepe(S3,V3,z.x,q.x); stepe(S3,V3,z.y,q.y);
            stepe(S3,V3,z.z,q.z); stepe(S4,V4,z.w,q.w);   // 32..34 | 35
#pragma unroll
            for (int j = 9; j < 15; j++) {           // elems 36..59
                z = rp[j]; q = sp[j];
                stepe(S4,V4,z.x,q.x); stepe(S4,V4,z.y,q.y);
                stepe(S4,V4,z.z,q.z); stepe(S4,V4,z.w,q.w);
            }
#pragma unroll
            for (int j = 15; j < 17; j++) {          // elems 60..67
                z = rp[j]; q = sp[j];
                stepe(S5,V5,z.x,q.x); stepe(S5,V5,z.y,q.y);
                stepe(S5,V5,z.z,q.z); stepe(S5,V5,z.w,q.w);
            }
            acc += fin(S0,V0, 1.f/3.f) + fin(S1,V1, 1.f/3.f)
                 + fin(S2,V2, 0.25f)   + fin(S3,V3, 0.04f)
                 + fin(S4,V4, 0.04f)   + fin(S5,V5, 0.125f);
        }
        __syncwarp();                    // all lanes done reading this stage

        // refill this stage with tile + 2*step
        const int nxt = tile + 2 * step;
        if (nxt < ntiles) {
            const float4* g = (const float4*)prev + (size_t)nxt * F4PW + lane;
            const int rows = min(TROWS, W - nxt * TROWS);
            if (rows == TROWS) {
#pragma unroll
                for (int k = 0; k < 17; k++) cp16(&bs[lane + 32 * k], g + 32 * k);
            } else {
                const int n4 = rows * 17;
#pragma unroll
                for (int k = 0; k < 17; k++)
                    if (lane + 32 * k < n4)  cp16(&bs[lane + 32 * k], g + 32 * k);
            }
        }
        cp_commit();
        stage ^= 1;
    }
    acc *= LN2;                          // log2 units -> nats

    // ---- per-warp reduction + last-warp-done final reduction ----
#pragma unroll
    for (int o = 16; o > 0; o >>= 1)
        acc += __shfl_xor_sync(0xffffffffu, acc, o);

    unsigned int is_last = 0;
    if (lane == 0) {
        g_partials[gw] = acc;
        __threadfence();
        unsigned int done = atomicAdd(&g_count, 1u);
        is_last = (done == (unsigned)nwarps - 1u) ? 1u : 0u;
    }
    is_last = __shfl_sync(0xffffffffu, is_last, 0);

    if (is_last) {
        float a = 0.f;
        for (int i = lane; i < nwarps; i += 32)  // fixed order: deterministic
            a += g_partials[i];
#pragma unroll
        for (int o = 16; o > 0; o >>= 1)
            a += __shfl_xor_sync(0xffffffffu, a, o);
        if (lane == 0) {
            out[0] = a * inv_W;
            g_count = 0;                 // reset for next graph replay
        }
    }
}

// ---------------------------------------------------------------------------
extern "C" void kernel_launch(void* const* d_in, const int* in_sizes, int n_in,
                              void* d_out, int out_size) {
    const float* cur  = (const float*)d_in[0];
    const float* prev = (const float*)d_in[1];
    float* out = (float*)d_out;

    int W = in_sizes[1] / A_TOT;
    int nblocks = 148 * 6;               // 888 blocks, 6/SM (smem-limited)
    if (nblocks * 2 > MAXW) nblocks = MAXW / 2;
    int nwarps = nblocks * 2;            // 1776 independent warp pipelines

    fused_kernel<<<nblocks, TPB>>>(cur, prev, out, W, nwarps, 1.0f / (float)W);
}

// round 11
// speedup vs baseline: 1.0985x; 1.0985x over previous
#include <cuda_runtime.h>
#include <cstdint>

#define A_TOT  68
#define TROWS  64
#define TPB    128
#define F4PT   (TROWS * 17)     // 1088 float4 per stage (17408 B)
#define STAGES 3
#define SMEMB  (STAGES * F4PT * 16)   // 52224 B dynamic
#define MAXB   2048
#define L2E    1.4426950408889634f
#define LN2    0.6931471805599453f

__device__ float g_partials[MAXB];
__device__ unsigned int g_count = 0;

__constant__ unsigned char c_seg_of[A_TOT] = {
    0,0,0, 1,1,1, 2,2,2,2,
    3,3,3,3,3,3,3,3,3,3,3,3,3,3,3,3,3,3,3,3,3,3,3,3,3,
    4,4,4,4,4,4,4,4,4,4,4,4,4,4,4,4,4,4,4,4,4,4,4,4,4,
    5,5,5,5,5,5,5,5
};
__constant__ int c_seg_beg[6] = {0, 3, 6, 10, 35, 60};
__constant__ int c_seg_end[6] = {3, 6, 10, 35, 60, 68};

// ---------------------------------------------------------------------------
__device__ __forceinline__ void cp16(void* sdst, const void* gsrc) {
    uint32_t s = (uint32_t)__cvta_generic_to_shared(sdst);
    asm volatile("cp.async.cg.shared.global [%0], [%1], 16;\n" :: "r"(s), "l"(gsrc));
}
__device__ __forceinline__ void cp_commit() { asm volatile("cp.async.commit_group;\n"); }
__device__ __forceinline__ void cp_wait1()  { asm volatile("cp.async.wait_group 1;\n"); }

__device__ __forceinline__ float ex2a(float x) {
    float r; asm("ex2.approx.f32 %0,%1;" : "=f"(r) : "f"(x)); return r;
}
__device__ __forceinline__ float lg2a(float x) {
    float r; asm("lg2.approx.f32 %0,%1;" : "=f"(r) : "f"(x)); return r;
}
__device__ __forceinline__ float rcpa(float x) {
    float r; asm("rcp.approx.f32 %0,%1;" : "=f"(r) : "f"(x)); return r;
}

// Per-element (log2 space; nxl = -x*log2e precomputed):
//   u = z*L2E; e = 2^u; S += e; V += e*(u+nxl)
// Segment loss (log2 units) = inv_n*(V/S - lg2 S); * ln2 once per thread.
__device__ __forceinline__ void stepe(float& S, float& V, float z, float nxl) {
    float u = z * L2E;
    float e = ex2a(u);
    S += e;
    V = fmaf(e, u + nxl, V);
}
__device__ __forceinline__ float fin(float S, float V, float inv_n) {
    return inv_n * fmaf(V, rcpa(S), -lg2a(S));
}

// prefetch one tile (tl) into stage s
__device__ __forceinline__ void prefetch_tile(float4* __restrict__ buf, int s,
                                              const float4* __restrict__ prevf4,
                                              int tl, int W, int t) {
    const float4* g = prevf4 + (size_t)tl * F4PT + t;
    float4* b = buf + s * F4PT;
    const int rows = min(TROWS, W - tl * TROWS);
    if (rows == TROWS) {
#pragma unroll
        for (int k = 0; k < 8; k++) cp16(&b[t + k * TPB], g + k * TPB);
        if (t < F4PT - 8 * TPB)     cp16(&b[t + 8 * TPB], g + 8 * TPB);
    } else {
        const int n4 = rows * 17;
#pragma unroll
        for (int k = 0; k < 9; k++)
            if (t + k * TPB < n4)   cp16(&b[t + k * TPB], g + k * TPB);
    }
}

// ---------------------------------------------------------------------------
// Depth-3 pipeline, ONE __syncthreads per round. Warps 0-1 -> segs 0..3
// (elems 0..34), warps 2-3 -> segs 4..5 (elems 35..67). sx table lives in
// registers (constant across tiles).
// ---------------------------------------------------------------------------
__global__ void __launch_bounds__(TPB, 4)
fused_kernel(const float* __restrict__ cur,
             const float* __restrict__ prev,
             float* __restrict__ out,
             int W, int nblocks, float inv_W) {
    extern __shared__ float4 buf[];          // [STAGES][F4PT] dynamic
    __shared__ float4 sxn[17];               // nxl = -x*log2e
    __shared__ float  scur[A_TOT];
    __shared__ float  sm6[6], sls6[6];
    __shared__ float  red[TPB / 32];
    __shared__ bool   s_last;

    const int t    = threadIdx.x;
    const int half = t >> 6;                 // 0: segs 0-3, 1: segs 4-5
    const int row  = t & 63;
    const int ntiles = (W + TROWS - 1) / TROWS;
    const int bid  = blockIdx.x;
    const float4* prevf4 = (const float4*)prev;

    const int nt = (ntiles - bid + nblocks - 1) / nblocks;   // rounds

    // ---- prefetch first two tiles ----
    if (nt > 0) prefetch_tile(buf, 0, prevf4, bid, W, t);
    cp_commit();
    if (nt > 1) prefetch_tile(buf, 1, prevf4, bid + nblocks, W, t);
    cp_commit();

    // ---- x-table: nxl = -(log2-space log_softmax(cur)) ----
    if (t < A_TOT) scur[t] = cur[t] * L2E;
    __syncthreads();
    if (t < 6) {
        int b = c_seg_beg[t], e = c_seg_end[t];
        float m = -1e30f;
        for (int i = b; i < e; i++) m = fmaxf(m, scur[i]);
        float sum = 0.f;
        for (int i = b; i < e; i++) sum += ex2a(scur[i] - m);
        sm6[t]  = m;
        sls6[t] = lg2a(sum);
    }
    __syncthreads();
    if (t < A_TOT) {
        int sg = c_seg_of[t];
        ((float*)sxn)[t] = -(scur[t] - sm6[sg] - sls6[sg]);
    }
    __syncthreads();

    // ---- hoist this thread's sx slice into registers (tile-invariant) ----
    const int off = half ? 8 : 0;
    float4 q0 = sxn[off + 0], q1 = sxn[off + 1], q2 = sxn[off + 2];
    float4 q3 = sxn[off + 3], q4 = sxn[off + 4], q5 = sxn[off + 5];
    float4 q6 = sxn[off + 6], q7 = sxn[off + 7], q8 = sxn[off + 8];

    // ---- main loop: one barrier per round, 2 tiles always in flight ----
    float acc = 0.f;                         // log2 units
    for (int it = 0; it < nt; it++) {
        cp_wait1();                          // tile(it) group complete
        __syncthreads();                     // visibility + reuse guard

        if (it + 2 < nt)
            prefetch_tile(buf, (it + 2) % STAGES, prevf4,
                          bid + (it + 2) * nblocks, W, t);
        cp_commit();                         // keep group sequence aligned

        const int tile = bid + it * nblocks;
        const int rows_here = min(TROWS, W - tile * TROWS);
        if (row < rows_here) {
            const float4* rp = buf + (it % STAGES) * F4PT + row * 17 + off;
            float4 z;
            if (half == 0) {
                float S0=0,V0=0, S1=0,V1=0, S2=0,V2=0, S3=0,V3=0;
                z = rp[0];
                stepe(S0,V0,z.x,q0.x); stepe(S0,V0,z.y,q0.y);
                stepe(S0,V0,z.z,q0.z); stepe(S1,V1,z.w,q0.w);
                z = rp[1];
                stepe(S1,V1,z.x,q1.x); stepe(S1,V1,z.y,q1.y);
                stepe(S2,V2,z.z,q1.z); stepe(S2,V2,z.w,q1.w);
                z = rp[2];
                stepe(S2,V2,z.x,q2.x); stepe(S2,V2,z.y,q2.y);
                stepe(S3,V3,z.z,q2.z); stepe(S3,V3,z.w,q2.w);
                z = rp[3];
                stepe(S3,V3,z.x,q3.x); stepe(S3,V3,z.y,q3.y);
                stepe(S3,V3,z.z,q3.z); stepe(S3,V3,z.w,q3.w);
                z = rp[4];
                stepe(S3,V3,z.x,q4.x); stepe(S3,V3,z.y,q4.y);
                stepe(S3,V3,z.z,q4.z); stepe(S3,V3,z.w,q4.w);
                z = rp[5];
                stepe(S3,V3,z.x,q5.x); stepe(S3,V3,z.y,q5.y);
                stepe(S3,V3,z.z,q5.z); stepe(S3,V3,z.w,q5.w);
                z = rp[6];
                stepe(S3,V3,z.x,q6.x); stepe(S3,V3,z.y,q6.y);
                stepe(S3,V3,z.z,q6.z); stepe(S3,V3,z.w,q6.w);
                z = rp[7];
                stepe(S3,V3,z.x,q7.x); stepe(S3,V3,z.y,q7.y);
                stepe(S3,V3,z.z,q7.z); stepe(S3,V3,z.w,q7.w);
                z = rp[8];
                stepe(S3,V3,z.x,q8.x); stepe(S3,V3,z.y,q8.y);
                stepe(S3,V3,z.z,q8.z);                      // elem 34
                acc += fin(S0,V0, 1.f/3.f) + fin(S1,V1, 1.f/3.f)
                     + fin(S2,V2, 0.25f)   + fin(S3,V3, 0.04f);
            } else {
                float S4=0,V4=0, S5=0,V5=0;
                z = rp[0];
                stepe(S4,V4,z.w,q0.w);                      // elem 35
                z = rp[1];
                stepe(S4,V4,z.x,q1.x); stepe(S4,V4,z.y,q1.y);
                stepe(S4,V4,z.z,q1.z); stepe(S4,V4,z.w,q1.w);
                z = rp[2];
                stepe(S4,V4,z.x,q2.x); stepe(S4,V4,z.y,q2.y);
                stepe(S4,V4,z.z,q2.z); stepe(S4,V4,z.w,q2.w);
                z = rp[3];
                stepe(S4,V4,z.x,q3.x); stepe(S4,V4,z.y,q3.y);
                stepe(S4,V4,z.z,q3.z); stepe(S4,V4,z.w,q3.w);
                z = rp[4];
                stepe(S4,V4,z.x,q4.x); stepe(S4,V4,z.y,q4.y);
                stepe(S4,V4,z.z,q4.z); stepe(S4,V4,z.w,q4.w);
                z = rp[5];
                stepe(S4,V4,z.x,q5.x); stepe(S4,V4,z.y,q5.y);
                stepe(S4,V4,z.z,q5.z); stepe(S4,V4,z.w,q5.w);
                z = rp[6];
                stepe(S4,V4,z.x,q6.x); stepe(S4,V4,z.y,q6.y);
                stepe(S4,V4,z.z,q6.z); stepe(S4,V4,z.w,q6.w);
                z = rp[7];
                stepe(S5,V5,z.x,q7.x); stepe(S5,V5,z.y,q7.y);
                stepe(S5,V5,z.z,q7.z); stepe(S5,V5,z.w,q7.w);
                z = rp[8];
                stepe(S5,V5,z.x,q8.x); stepe(S5,V5,z.y,q8.y);
                stepe(S5,V5,z.z,q8.z); stepe(S5,V5,z.w,q8.w);
                acc += fin(S4,V4, 0.04f) + fin(S5,V5, 0.125f);
            }
        }
    }
    acc *= LN2;                              // log2 units -> nats

    // ---- deterministic block reduction (4 warps) ----
#pragma unroll
    for (int o = 16; o > 0; o >>= 1)
        acc += __shfl_xor_sync(0xffffffffu, acc, o);
    if ((t & 31) == 0) red[t >> 5] = acc;
    __syncthreads();

    if (t == 0) {
        g_partials[blockIdx.x] = red[0] + red[1] + red[2] + red[3];
        __threadfence();
        unsigned int done = atomicAdd(&g_count, 1u);
        s_last = (done == (unsigned)nblocks - 1u);
    }
    __syncthreads();

    // ---- last block: deterministic final reduction (fixed strided order) ----
    if (s_last) {
        float a = 0.f;
        for (int i = t; i < nblocks; i += TPB)
            a += g_partials[i];
#pragma unroll
        for (int o = 16; o > 0; o >>= 1)
            a += __shfl_xor_sync(0xffffffffu, a, o);
        if ((t & 31) == 0) red[t >> 5] = a;
        __syncthreads();
        if (t == 0) {
            out[0] = (red[0] + red[1] + red[2] + red[3]) * inv_W;
            g_count = 0;     // reset for next graph replay
        }
    }
}

// ---------------------------------------------------------------------------
extern "C" void kernel_launch(void* const* d_in, const int* in_sizes, int n_in,
                              void* d_out, int out_size) {
    const float* cur  = (const float*)d_in[0];
    const float* prev = (const float*)d_in[1];
    float* out = (float*)d_out;

    int W = in_sizes[1] / A_TOT;
    int nblocks = 148 * 4;                   // 4 blocks/SM (52.2KB smem each)
    if (nblocks > MAXB) nblocks = MAXB;
    int ntiles = (W + TROWS - 1) / TROWS;
    if (nblocks > ntiles) nblocks = ntiles;

    cudaFuncSetAttribute(fused_kernel,
                         cudaFuncAttributeMaxDynamicSharedMemorySize, SMEMB);
    fused_kernel<<<nblocks, TPB, SMEMB>>>(cur, prev, out, W, nblocks,
                                          1.0f / (float)W);
}